// round 12
// baseline (speedup 1.0000x reference)
#include <cuda_runtime.h>
#include <math_constants.h>
#include <cstdint>

#define NPTS 16384
#define LSZ  11
#define FULLM 0xffffffffu

#define NCELLS 4096            // 16^3 fine grid
#define DOMLO  -4.5f
#define CW     0.5625f         // fine cell width  (9/16)
#define SW     2.25f           // super cell width (9/4)
#define MARGIN 1e-3f
#define CAP    64              // per-list candidate buffer capacity
#define WPB    4               // warps per block

__device__ float4 g_pts[2][NPTS];     // sorted by cell: x,y,z,sq (XLA rounding)
__device__ int    g_oidx[2][NPTS];    // sorted pos -> original index
__device__ int    g_start[2][NCELLS];
__device__ int    g_cnt[2][NCELLS];
__device__ int    g_cur[2][NCELLS];

__device__ __forceinline__ int cell_coord(float x) {
    int c = (int)floorf((x - DOMLO) * (1.0f / CW));
    return min(15, max(0, c));
}

// ---------------- wide setup: zero+hist, scan, scatter ----------------
__global__ void hist_kernel(const float* __restrict__ sc, const float* __restrict__ tc) {
    int j = blockIdx.x * blockDim.x + threadIdx.x;
    if (j < 2 * NCELLS) (&g_cnt[0][0])[j] = 0;   // grid covers both; zero first wave
    __syncthreads();
    // separate grid-stride pass after zero is unsafe across blocks; instead zero
    // is done by the first 8192 threads of this grid BEFORE any atomics only if
    // the same block zeroed the cells it touches — not guaranteed. So: zero in
    // its own kernel below. (This kernel body replaced at launch site.)
}

__global__ void zero_kernel() {
    int i = blockIdx.x * blockDim.x + threadIdx.x;
    if (i < 2 * NCELLS) (&g_cnt[0][0])[i] = 0;
}

__global__ void count_kernel(const float* __restrict__ sc, const float* __restrict__ tc) {
    int j = blockIdx.x * blockDim.x + threadIdx.x;
    if (j >= NPTS) return;
    int cloud = blockIdx.y;
    const float* __restrict__ c = cloud ? tc : sc;
    int cx = cell_coord(c[3 * j + 0]);
    int cy = cell_coord(c[3 * j + 1]);
    int cz = cell_coord(c[3 * j + 2]);
    atomicAdd(&g_cnt[cloud][(cz << 8) | (cy << 4) | cx], 1);
}

__global__ __launch_bounds__(512) void scan_kernel() {
    int cloud = blockIdx.x;
    int t = threadIdx.x;                 // 512 threads, 8 cells each
    __shared__ int sh[512];
    int loc[8];
    int sum = 0;
    #pragma unroll
    for (int i = 0; i < 8; i++) { loc[i] = g_cnt[cloud][t * 8 + i]; sum += loc[i]; }
    sh[t] = sum;
    __syncthreads();
    for (int off = 1; off < 512; off <<= 1) {
        int v = (t >= off) ? sh[t - off] : 0;
        __syncthreads();
        sh[t] += v;
        __syncthreads();
    }
    int excl = sh[t] - sum;
    #pragma unroll
    for (int i = 0; i < 8; i++) {
        g_start[cloud][t * 8 + i] = excl;
        g_cur[cloud][t * 8 + i] = excl;
        excl += loc[i];
    }
}

__global__ void scatter_kernel(const float* __restrict__ sc, const float* __restrict__ tc) {
    int j = blockIdx.x * blockDim.x + threadIdx.x;
    if (j >= NPTS) return;
    int cloud = blockIdx.y;
    const float* __restrict__ c = cloud ? tc : sc;
    float x = c[3 * j + 0];
    float y = c[3 * j + 1];
    float z = c[3 * j + 2];
    // XLA multi-row warp reduction order: ((x*x + z*z) + y*y), each op rounded
    float sq = __fadd_rn(__fadd_rn(__fmul_rn(x, x), __fmul_rn(z, z)), __fmul_rn(y, y));
    int cell = (cell_coord(z) << 8) | (cell_coord(y) << 4) | cell_coord(x);
    int pos = atomicAdd(&g_cur[cloud][cell], 1);
    g_pts[cloud][pos] = make_float4(x, y, z, sq);
    g_oidx[cloud][pos] = j;
}

// ---------------- knn kernel (R11-proven body) ----------------
__device__ __forceinline__ float lb_box(const float4& p, int cx, int cy, int cz,
                                        float w, int cmax) {
    float lox = (cx == 0)    ? -CUDART_INF_F : __fmaf_rn((float)cx, w, DOMLO);
    float hix = (cx == cmax) ?  CUDART_INF_F : __fmaf_rn((float)(cx + 1), w, DOMLO);
    float loy = (cy == 0)    ? -CUDART_INF_F : __fmaf_rn((float)cy, w, DOMLO);
    float hiy = (cy == cmax) ?  CUDART_INF_F : __fmaf_rn((float)(cy + 1), w, DOMLO);
    float loz = (cz == 0)    ? -CUDART_INF_F : __fmaf_rn((float)cz, w, DOMLO);
    float hiz = (cz == cmax) ?  CUDART_INF_F : __fmaf_rn((float)(cz + 1), w, DOMLO);
    float dx = p.x - fminf(fmaxf(p.x, lox), hix);
    float dy = p.y - fminf(fmaxf(p.y, loy), hiy);
    float dz = p.z - fminf(fmaxf(p.z, loz), hiz);
    return __fmaf_rn(dx, dx, __fmaf_rn(dy, dy, dz * dz));
}

__device__ __forceinline__ unsigned long long packdi(float d, int idx) {
    unsigned u = __float_as_uint(d);
    u ^= ((unsigned)((int)u >> 31)) | 0x80000000u;
    return ((unsigned long long)u << 32) | (unsigned)idx;
}

__device__ __forceinline__ float unpackd(unsigned hi) {
    return (hi & 0x80000000u) ? __uint_as_float(hi ^ 0x80000000u)
                              : __uint_as_float(~hi);
}

// Rank-select: keep the LSZ smallest (sorted at buf[0..LSZ-1]), update threshold.
__device__ __forceinline__ void compress(unsigned long long* buf, int& cnt, float& tf,
                                         int lane) {
    __syncwarp();
    int n = cnt;
    unsigned long long v0 = (lane < n) ? buf[lane] : 0xFFFFFFFFFFFFFFFFull;
    unsigned long long v1 = (lane + 32 < n) ? buf[lane + 32] : 0xFFFFFFFFFFFFFFFFull;
    int r0 = 0, r1 = 0;
    for (int j = 0; j < n; j++) {
        unsigned long long bj = buf[j];
        r0 += (bj < v0);
        r1 += (bj < v1);
    }
    __syncwarp();
    if (lane < n && r0 < LSZ) buf[r0] = v0;
    if (lane + 32 < n && r1 < LSZ) buf[r1] = v1;
    __syncwarp();
    if (n >= LSZ) {
        tf = unpackd((unsigned)(buf[LSZ - 1] >> 32));
        cnt = LSZ;
    }
}

__device__ __forceinline__ void collect_range(int cloud, int start, int end, int lane,
        const float4 pA, const float4 pB,
        unsigned long long* bufA, unsigned long long* bufB,
        int& cntA, int& cntB, float& tfA, float& tfB) {
    for (int base = start; base < end; base += 32) {
        int k = base + lane;
        bool vld = k < end;
        int kc = vld ? k : start;
        float4 c = g_pts[cloud][kc];
        // dist = fl( fl(sq_i + sq_j) - 2*dot ), dot = fma(z,z', fma(y,y', x*x'))
        float dotA = __fmaf_rn(pA.z, c.z, __fmaf_rn(pA.y, c.y, __fmul_rn(pA.x, c.x)));
        float dotB = __fmaf_rn(pB.z, c.z, __fmaf_rn(pB.y, c.y, __fmul_rn(pB.x, c.x)));
        float dA = __fmaf_rn(-2.0f, dotA, __fadd_rn(pA.w, c.w));
        float dB = __fmaf_rn(-2.0f, dotB, __fadd_rn(pB.w, c.w));
        bool sA = vld && (dA <= tfA);
        bool sB = vld && (dB <= tfB);
        if (!__ballot_sync(FULLM, sA || sB)) continue;   // common fast path
        int jo = g_oidx[cloud][kc];
        unsigned mA = __ballot_sync(FULLM, sA);
        unsigned mB = __ballot_sync(FULLM, sB);
        if (mA) {
            if (cntA >= 32) compress(bufA, cntA, tfA, lane);   // early tf tighten
            int ofs = cntA + __popc(mA & ((1u << lane) - 1));
            if (sA) bufA[ofs] = packdi(dA, jo);
            cntA += __popc(mA);
        }
        if (mB) {
            if (cntB >= 32) compress(bufB, cntB, tfB, lane);
            int ofs = cntB + __popc(mB & ((1u << lane) - 1));
            if (sB) bufB[ofs] = packdi(dB, jo);
            cntB += __popc(mB);
        }
    }
}

__global__ __launch_bounds__(32 * WPB, 10) void knn_kernel(const float* __restrict__ src,
                                                           const float* __restrict__ tgt,
                                                           float* __restrict__ out) {
    __shared__ unsigned long long sbuf[WPB][2][CAP];

    const int cloud = blockIdx.y;
    const int warp  = threadIdx.x >> 5;
    const int lane  = threadIdx.x & 31;
    const int p0 = blockIdx.x * (2 * WPB) + warp * 2;   // sorted positions
    const int p1 = p0 + 1;

    const float4 pA = g_pts[cloud][p0];
    const float4 pB = g_pts[cloud][p1];
    const int cellA = (cell_coord(pA.z) << 8) | (cell_coord(pA.y) << 4) | cell_coord(pA.x);
    const int cellB = (cell_coord(pB.z) << 8) | (cell_coord(pB.y) << 4) | cell_coord(pB.x);

    unsigned long long* bufA = sbuf[warp][0];
    unsigned long long* bufB = sbuf[warp][1];
    int   cntA = 0, cntB = 0;
    float tfA = CUDART_INF_F, tfB = CUDART_INF_F;

    // Own cell(s) first to tighten thresholds
    {
        int st = g_start[cloud][cellA];
        collect_range(cloud, st, st + g_cnt[cloud][cellA], lane, pA, pB,
                      bufA, bufB, cntA, cntB, tfA, tfB);
        if (cellB != cellA) {
            int st2 = g_start[cloud][cellB];
            collect_range(cloud, st2, st2 + g_cnt[cloud][cellB], lane, pA, pB,
                          bufA, bufB, cntA, cntB, tfA, tfB);
        }
        if (cntA > LSZ) compress(bufA, cntA, tfA, lane);
        if (cntB > LSZ) compress(bufB, cntB, tfB, lane);
    }

    // Supercell sweep (64 supers in 2 lane-parallel iterations)
    #pragma unroll
    for (int t = 0; t < 2; t++) {
        int s = t * 32 + lane;
        int sx = s & 3, sy = (s >> 2) & 3, sz = (s >> 4) & 3;
        float lA = lb_box(pA, sx, sy, sz, SW, 3);
        float lB = lb_box(pB, sx, sy, sz, SW, 3);
        unsigned msup = __ballot_sync(FULLM, (lA <= tfA + MARGIN) || (lB <= tfB + MARGIN));
        while (msup) {
            int sb = __ffs(msup) - 1; msup &= msup - 1;
            int S = t * 32 + sb;
            int fx0 = (S & 3) * 4, fy0 = ((S >> 2) & 3) * 4, fz0 = ((S >> 4) & 3) * 4;
            #pragma unroll
            for (int u = 0; u < 2; u++) {
                int cidx = u * 32 + lane;
                int fx = fx0 + (cidx & 3), fy = fy0 + ((cidx >> 2) & 3), fz = fz0 + ((cidx >> 4) & 3);
                int f = (fz << 8) | (fy << 4) | fx;
                float fA = lb_box(pA, fx, fy, fz, CW, 15);
                float fB = lb_box(pB, fx, fy, fz, CW, 15);
                bool pass = (f != cellA) && (f != cellB) && (g_cnt[cloud][f] > 0) &&
                            ((fA <= tfA + MARGIN) || (fB <= tfB + MARGIN));
                unsigned mf = __ballot_sync(FULLM, pass);
                while (mf) {
                    // merge runs of x-adjacent surviving cells (contiguous ranges)
                    int b = __ffs(mf) - 1;
                    int e = b;
                    while (e < 31 && ((mf >> (e + 1)) & 1u) && (((e + 1) & 3) != 0)) e++;
                    unsigned run = ((e == 31) ? 0xFFFFFFFFu : ((1u << (e + 1)) - 1u))
                                   & ~((1u << b) - 1u);
                    mf &= ~run;
                    int f0 = __shfl_sync(FULLM, f, b);
                    int f1 = __shfl_sync(FULLM, f, e);
                    int st = g_start[cloud][f0];
                    int en = g_start[cloud][f1] + g_cnt[cloud][f1];
                    collect_range(cloud, st, en, lane, pA, pB,
                                  bufA, bufB, cntA, cntB, tfA, tfB);
                }
            }
        }
    }

    // Final exact selection: sorted top-11 at buf[0..10]
    compress(bufA, cntA, tfA, lane);
    compress(bufB, cntB, tfB, lane);
    __syncwarp();

    // Epilogue: drop rank 0 (self); rank r in 1..10 contributes feats[idx_r, r-1]
    const float* __restrict__ feats = cloud ? tgt : src;
    const int iAo = g_oidx[cloud][p0];
    const int iBo = g_oidx[cloud][p1];

    float v = -CUDART_INF_F;
    if (lane >= 1 && lane < LSZ) {
        int li = (int)(unsigned)bufA[lane];
        v = feats[(size_t)li * 64 + (lane - 1)];
    } else if (lane >= 17 && lane < 16 + LSZ) {
        int li = (int)(unsigned)bufB[lane - 16];
        v = feats[(size_t)li * 64 + (lane - 17)];
    }
    #pragma unroll
    for (int m = 8; m; m >>= 1)
        v = fmaxf(v, __shfl_xor_sync(FULLM, v, m));   // half-warp reductions
    float maxA = __shfl_sync(FULLM, v, 0);
    float maxB = __shfl_sync(FULLM, v, 16);

    const float2* __restrict__ fA = (const float2*)(feats + (size_t)iAo * 64);
    const float2* __restrict__ fB = (const float2*)(feats + (size_t)iBo * 64);
    float2* oA = (float2*)(out + ((size_t)cloud * NPTS + iAo) * 128);
    float2* oB = (float2*)(out + ((size_t)cloud * NPTS + iBo) * 128);
    float2 a = fA[lane];
    float2 b = fB[lane];
    oA[lane] = a;
    oB[lane] = b;
    float2 da, db;
    da.x = __fsub_rn(maxA, a.x);  da.y = __fsub_rn(maxA, a.y);
    db.x = __fsub_rn(maxB, b.x);  db.y = __fsub_rn(maxB, b.y);
    oA[32 + lane] = da;
    oB[32 + lane] = db;
}

extern "C" void kernel_launch(void* const* d_in, const int* in_sizes, int n_in,
                              void* d_out, int out_size) {
    const float* src = (const float*)d_in[0];
    const float* tgt = (const float*)d_in[1];
    const float* sc  = (const float*)d_in[2];
    const float* tc  = (const float*)d_in[3];
    float* out = (float*)d_out;

    zero_kernel<<<8, 1024>>>();
    count_kernel<<<dim3(64, 2), 256>>>(sc, tc);
    scan_kernel<<<2, 512>>>();
    scatter_kernel<<<dim3(64, 2), 256>>>(sc, tc);
    knn_kernel<<<dim3(NPTS / (2 * WPB), 2), 32 * WPB>>>(src, tgt, out);
}

// round 14
// speedup vs baseline: 1.1479x; 1.1479x over previous
#include <cuda_runtime.h>
#include <math_constants.h>
#include <cstdint>

#define NPTS 16384
#define LSZ  11
#define FULLM 0xffffffffu

#define NCELLS 4096            // 16^3 fine grid
#define DOMLO  -4.5f
#define CW     0.5625f         // fine cell width  (9/16)
#define SW     2.25f           // super cell width (9/4)
#define MARGIN 1e-3f
#define CAP    64              // per-list candidate buffer capacity
#define WPB    4               // warps per block
#define NGRP   (NPTS / (2 * WPB))   // 2048 groups of 8 points

__device__ float4 g_pts[2][NPTS];        // sorted by cell: x,y,z,sq (XLA rounding)
__device__ int    g_oidx[2][NPTS];       // sorted pos -> original index
__device__ int    g_start[2][NCELLS + 1];// prefix starts + sentinel NPTS
__device__ int    g_cnt[2][NCELLS];      // ALWAYS zero at kernel_launch entry
__device__ int    g_cur[2][NCELLS];

__device__ __forceinline__ int cell_coord(float x) {
    int c = (int)floorf((x - DOMLO) * (1.0f / CW));
    return min(15, max(0, c));
}

// ---------------- setup: count, scan(+re-zero), scatter ----------------
__global__ void count_kernel(const float* __restrict__ sc, const float* __restrict__ tc) {
    int j = blockIdx.x * blockDim.x + threadIdx.x;
    if (j >= NPTS) return;
    int cloud = blockIdx.y;
    const float* __restrict__ c = cloud ? tc : sc;
    int cx = cell_coord(c[3 * j + 0]);
    int cy = cell_coord(c[3 * j + 1]);
    int cz = cell_coord(c[3 * j + 2]);
    atomicAdd(&g_cnt[cloud][(cz << 8) | (cy << 4) | cx], 1);
}

__global__ __launch_bounds__(512) void scan_kernel() {
    int cloud = blockIdx.x;
    int t = threadIdx.x;                 // 512 threads, 8 cells each
    __shared__ int sh[512];
    int loc[8];
    int sum = 0;
    #pragma unroll
    for (int i = 0; i < 8; i++) {
        loc[i] = g_cnt[cloud][t * 8 + i];
        g_cnt[cloud][t * 8 + i] = 0;     // restore invariant for next launch
        sum += loc[i];
    }
    sh[t] = sum;
    __syncthreads();
    for (int off = 1; off < 512; off <<= 1) {
        int v = (t >= off) ? sh[t - off] : 0;
        __syncthreads();
        sh[t] += v;
        __syncthreads();
    }
    int excl = sh[t] - sum;
    #pragma unroll
    for (int i = 0; i < 8; i++) {
        g_start[cloud][t * 8 + i] = excl;
        g_cur[cloud][t * 8 + i] = excl;
        excl += loc[i];
    }
    if (t == 511) g_start[cloud][NCELLS] = NPTS;   // sentinel
}

__global__ void scatter_kernel(const float* __restrict__ sc, const float* __restrict__ tc) {
    int j = blockIdx.x * blockDim.x + threadIdx.x;
    if (j >= NPTS) return;
    int cloud = blockIdx.y;
    const float* __restrict__ c = cloud ? tc : sc;
    float x = c[3 * j + 0];
    float y = c[3 * j + 1];
    float z = c[3 * j + 2];
    // XLA multi-row warp reduction order: ((x*x + z*z) + y*y), each op rounded
    float sq = __fadd_rn(__fadd_rn(__fmul_rn(x, x), __fmul_rn(z, z)), __fmul_rn(y, y));
    int cell = (cell_coord(z) << 8) | (cell_coord(y) << 4) | cell_coord(x);
    int pos = atomicAdd(&g_cur[cloud][cell], 1);
    g_pts[cloud][pos] = make_float4(x, y, z, sq);
    g_oidx[cloud][pos] = j;
}

// ---------------- knn kernel (R11-proven body; wave-balanced blocks) ----------------
__device__ __forceinline__ float lb_box(const float4& p, int cx, int cy, int cz,
                                        float w, int cmax) {
    float lox = (cx == 0)    ? -CUDART_INF_F : __fmaf_rn((float)cx, w, DOMLO);
    float hix = (cx == cmax) ?  CUDART_INF_F : __fmaf_rn((float)(cx + 1), w, DOMLO);
    float loy = (cy == 0)    ? -CUDART_INF_F : __fmaf_rn((float)cy, w, DOMLO);
    float hiy = (cy == cmax) ?  CUDART_INF_F : __fmaf_rn((float)(cy + 1), w, DOMLO);
    float loz = (cz == 0)    ? -CUDART_INF_F : __fmaf_rn((float)cz, w, DOMLO);
    float hiz = (cz == cmax) ?  CUDART_INF_F : __fmaf_rn((float)(cz + 1), w, DOMLO);
    float dx = p.x - fminf(fmaxf(p.x, lox), hix);
    float dy = p.y - fminf(fmaxf(p.y, loy), hiy);
    float dz = p.z - fminf(fmaxf(p.z, loz), hiz);
    return __fmaf_rn(dx, dx, __fmaf_rn(dy, dy, dz * dz));
}

__device__ __forceinline__ unsigned long long packdi(float d, int idx) {
    unsigned u = __float_as_uint(d);
    u ^= ((unsigned)((int)u >> 31)) | 0x80000000u;
    return ((unsigned long long)u << 32) | (unsigned)idx;
}

__device__ __forceinline__ float unpackd(unsigned hi) {
    return (hi & 0x80000000u) ? __uint_as_float(hi ^ 0x80000000u)
                              : __uint_as_float(~hi);
}

// Rank-select: keep the LSZ smallest (sorted at buf[0..LSZ-1]), update threshold.
__device__ __forceinline__ void compress(unsigned long long* buf, int& cnt, float& tf,
                                         int lane) {
    __syncwarp();
    int n = cnt;
    unsigned long long v0 = (lane < n) ? buf[lane] : 0xFFFFFFFFFFFFFFFFull;
    unsigned long long v1 = (lane + 32 < n) ? buf[lane + 32] : 0xFFFFFFFFFFFFFFFFull;
    int r0 = 0, r1 = 0;
    for (int j = 0; j < n; j++) {
        unsigned long long bj = buf[j];
        r0 += (bj < v0);
        r1 += (bj < v1);
    }
    __syncwarp();
    if (lane < n && r0 < LSZ) buf[r0] = v0;
    if (lane + 32 < n && r1 < LSZ) buf[r1] = v1;
    __syncwarp();
    if (n >= LSZ) {
        tf = unpackd((unsigned)(buf[LSZ - 1] >> 32));
        cnt = LSZ;
    }
}

__device__ __forceinline__ void collect_range(int cloud, int start, int end, int lane,
        const float4 pA, const float4 pB,
        unsigned long long* bufA, unsigned long long* bufB,
        int& cntA, int& cntB, float& tfA, float& tfB) {
    for (int base = start; base < end; base += 32) {
        int k = base + lane;
        bool vld = k < end;
        int kc = vld ? k : start;
        float4 c = g_pts[cloud][kc];
        // dist = fl( fl(sq_i + sq_j) - 2*dot ), dot = fma(z,z', fma(y,y', x*x'))
        float dotA = __fmaf_rn(pA.z, c.z, __fmaf_rn(pA.y, c.y, __fmul_rn(pA.x, c.x)));
        float dotB = __fmaf_rn(pB.z, c.z, __fmaf_rn(pB.y, c.y, __fmul_rn(pB.x, c.x)));
        float dA = __fmaf_rn(-2.0f, dotA, __fadd_rn(pA.w, c.w));
        float dB = __fmaf_rn(-2.0f, dotB, __fadd_rn(pB.w, c.w));
        bool sA = vld && (dA <= tfA);
        bool sB = vld && (dB <= tfB);
        if (!__ballot_sync(FULLM, sA || sB)) continue;   // common fast path
        int jo = g_oidx[cloud][kc];
        unsigned mA = __ballot_sync(FULLM, sA);
        unsigned mB = __ballot_sync(FULLM, sB);
        if (mA) {
            if (cntA >= 32) compress(bufA, cntA, tfA, lane);   // early tf tighten
            int ofs = cntA + __popc(mA & ((1u << lane) - 1));
            if (sA) bufA[ofs] = packdi(dA, jo);
            cntA += __popc(mA);
        }
        if (mB) {
            if (cntB >= 32) compress(bufB, cntB, tfB, lane);
            int ofs = cntB + __popc(mB & ((1u << lane) - 1));
            if (sB) bufB[ofs] = packdi(dB, jo);
            cntB += __popc(mB);
        }
    }
}

__global__ __launch_bounds__(32 * WPB) void knn_kernel(const float* __restrict__ src,
                                                       const float* __restrict__ tgt,
                                                       float* __restrict__ out) {
    __shared__ unsigned long long sbuf[WPB][2][CAP];

    const int cloud = blockIdx.y;
    const int warp  = threadIdx.x >> 5;
    const int lane  = threadIdx.x & 31;
    // Wave-balancing permutation: scatter dense (central) groups across launch order
    const int grp = (int)(((unsigned)blockIdx.x * 593u) & (NGRP - 1));
    const int p0 = grp * (2 * WPB) + warp * 2;   // sorted positions
    const int p1 = p0 + 1;

    const float4 pA = g_pts[cloud][p0];
    const float4 pB = g_pts[cloud][p1];
    const int cellA = (cell_coord(pA.z) << 8) | (cell_coord(pA.y) << 4) | cell_coord(pA.x);
    const int cellB = (cell_coord(pB.z) << 8) | (cell_coord(pB.y) << 4) | cell_coord(pB.x);

    const int* __restrict__ cst = g_start[cloud];
    unsigned long long* bufA = sbuf[warp][0];
    unsigned long long* bufB = sbuf[warp][1];
    int   cntA = 0, cntB = 0;
    float tfA = CUDART_INF_F, tfB = CUDART_INF_F;

    // Own cell(s) first to tighten thresholds
    {
        collect_range(cloud, cst[cellA], cst[cellA + 1], lane, pA, pB,
                      bufA, bufB, cntA, cntB, tfA, tfB);
        if (cellB != cellA)
            collect_range(cloud, cst[cellB], cst[cellB + 1], lane, pA, pB,
                          bufA, bufB, cntA, cntB, tfA, tfB);
        if (cntA > LSZ) compress(bufA, cntA, tfA, lane);
        if (cntB > LSZ) compress(bufB, cntB, tfB, lane);
    }

    // Supercell sweep (64 supers in 2 lane-parallel iterations)
    #pragma unroll
    for (int t = 0; t < 2; t++) {
        int s = t * 32 + lane;
        int sx = s & 3, sy = (s >> 2) & 3, sz = (s >> 4) & 3;
        float lA = lb_box(pA, sx, sy, sz, SW, 3);
        float lB = lb_box(pB, sx, sy, sz, SW, 3);
        unsigned msup = __ballot_sync(FULLM, (lA <= tfA + MARGIN) || (lB <= tfB + MARGIN));
        while (msup) {
            int sb = __ffs(msup) - 1; msup &= msup - 1;
            int S = t * 32 + sb;
            int fx0 = (S & 3) * 4, fy0 = ((S >> 2) & 3) * 4, fz0 = ((S >> 4) & 3) * 4;
            #pragma unroll
            for (int u = 0; u < 2; u++) {
                int cidx = u * 32 + lane;
                int fx = fx0 + (cidx & 3), fy = fy0 + ((cidx >> 2) & 3), fz = fz0 + ((cidx >> 4) & 3);
                int f = (fz << 8) | (fy << 4) | fx;
                float fA = lb_box(pA, fx, fy, fz, CW, 15);
                float fB = lb_box(pB, fx, fy, fz, CW, 15);
                bool pass = (f != cellA) && (f != cellB) && (cst[f + 1] > cst[f]) &&
                            ((fA <= tfA + MARGIN) || (fB <= tfB + MARGIN));
                unsigned mf = __ballot_sync(FULLM, pass);
                while (mf) {
                    // merge runs of x-adjacent surviving cells (contiguous ranges)
                    int b = __ffs(mf) - 1;
                    int e = b;
                    while (e < 31 && ((mf >> (e + 1)) & 1u) && (((e + 1) & 3) != 0)) e++;
                    unsigned run = ((e == 31) ? 0xFFFFFFFFu : ((1u << (e + 1)) - 1u))
                                   & ~((1u << b) - 1u);
                    mf &= ~run;
                    int f0 = __shfl_sync(FULLM, f, b);
                    int f1 = __shfl_sync(FULLM, f, e);
                    collect_range(cloud, cst[f0], cst[f1 + 1], lane, pA, pB,
                                  bufA, bufB, cntA, cntB, tfA, tfB);
                }
            }
        }
    }

    // Final exact selection: sorted top-11 at buf[0..10]
    compress(bufA, cntA, tfA, lane);
    compress(bufB, cntB, tfB, lane);
    __syncwarp();

    // Epilogue: drop rank 0 (self); rank r in 1..10 contributes feats[idx_r, r-1]
    const float* __restrict__ feats = cloud ? tgt : src;
    const int iAo = g_oidx[cloud][p0];
    const int iBo = g_oidx[cloud][p1];

    float v = -CUDART_INF_F;
    if (lane >= 1 && lane < LSZ) {
        int li = (int)(unsigned)bufA[lane];
        v = feats[(size_t)li * 64 + (lane - 1)];
    } else if (lane >= 17 && lane < 16 + LSZ) {
        int li = (int)(unsigned)bufB[lane - 16];
        v = feats[(size_t)li * 64 + (lane - 17)];
    }
    #pragma unroll
    for (int m = 8; m; m >>= 1)
        v = fmaxf(v, __shfl_xor_sync(FULLM, v, m));   // half-warp reductions
    float maxA = __shfl_sync(FULLM, v, 0);
    float maxB = __shfl_sync(FULLM, v, 16);

    const float2* __restrict__ fA = (const float2*)(feats + (size_t)iAo * 64);
    const float2* __restrict__ fB = (const float2*)(feats + (size_t)iBo * 64);
    float2* oA = (float2*)(out + ((size_t)cloud * NPTS + iAo) * 128);
    float2* oB = (float2*)(out + ((size_t)cloud * NPTS + iBo) * 128);
    float2 a = fA[lane];
    float2 b = fB[lane];
    oA[lane] = a;
    oB[lane] = b;
    float2 da, db;
    da.x = __fsub_rn(maxA, a.x);  da.y = __fsub_rn(maxA, a.y);
    db.x = __fsub_rn(maxB, b.x);  db.y = __fsub_rn(maxB, b.y);
    oA[32 + lane] = da;
    oB[32 + lane] = db;
}

extern "C" void kernel_launch(void* const* d_in, const int* in_sizes, int n_in,
                              void* d_out, int out_size) {
    const float* src = (const float*)d_in[0];
    const float* tgt = (const float*)d_in[1];
    const float* sc  = (const float*)d_in[2];
    const float* tc  = (const float*)d_in[3];
    float* out = (float*)d_out;

    count_kernel<<<dim3(64, 2), 256>>>(sc, tc);
    scan_kernel<<<2, 512>>>();
    scatter_kernel<<<dim3(64, 2), 256>>>(sc, tc);
    knn_kernel<<<dim3(NGRP, 2), 32 * WPB>>>(src, tgt, out);
}